// round 4
// baseline (speedup 1.0000x reference)
#include <cuda_runtime.h>
#include <mma.h>
#include <math.h>

using namespace nvcuda;

#define N_NODES 50000
#define N_EDGES 600000
#define H 128
#define H13 (13 * H)
#define LOG17 2.8332133440562162f

// ---------------- scratch (static device globals; no allocation) ----------------
__device__ float g_xd[(size_t)N_NODES * H];    // x @ Wpre[0:H]    (reused as ys)
__device__ float g_xs[(size_t)N_NODES * H];    // x @ Wpre[H:2H]   (reused as yd)
__device__ float g_h[(size_t)N_EDGES * H];     // per-edge message (reused as z)
__device__ float g_A13[(size_t)N_NODES * H13]; // cat[x, scaled]
__device__ float g_outb[(size_t)N_NODES * H];  // pre-BN node output
__device__ float g_Wef[H * H];                 // We @ Wpre[2H:3H]
__device__ float g_W13[H13 * H];               // Wpost @ Wlin
__device__ float g_bh[H];
__device__ float g_b13[H];
__device__ int   g_deg[N_NODES];
__device__ int   g_off[N_NODES + 1];
__device__ int   g_cur[N_NODES];
__device__ int   g_perm[N_EDGES];
__device__ float g_bnsum[H];
__device__ float g_bnsq[H];
__device__ float g_mu[H];
__device__ float g_istd[H];

// ============ TF32 WMMA GEMM: C[M,128] = A[M,K] @ B[K,128] ============
// MODE 0: C = acc (+bias)
// MODE 1: C = acc + bias + P[i1[row]] + Q[i2[row]]
// MODE 2: C = relu(acc + bias + P[i1[row]] + Q[i2[row]])
// MODE 3: C = R[row] + (acc + bias) * 0.5
// Tile: 128x128 per CTA, 8 warps, warp tile 32x64 = 2x4 wmma m16n16k8 frags.
// BK=32 single-buffered staging, padded strides. No inline PTX anywhere.

#define AS_STRIDE 36
#define BS_STRIDE 136

template <int MODE>
__global__ void __launch_bounds__(256) wgemm(
    const float* __restrict__ A, int lda,
    const float* __restrict__ B,
    const float* __restrict__ bias,
    float* __restrict__ C, int M, int K,
    const int* __restrict__ i1, const int* __restrict__ i2,
    const float* __restrict__ P, const float* __restrict__ Q,
    const float* __restrict__ R)
{
    __shared__ float As[128 * AS_STRIDE];   // 18.0 KB
    __shared__ float Bs[32 * BS_STRIDE];    // 17.0 KB
    __shared__ float Cs[8][256];            //  8.0 KB  (per-warp epilogue scratch)

    const int tid = threadIdx.x;
    const int wid = tid >> 5;
    const int lane = tid & 31;
    const int row0 = blockIdx.x * 128;
    const int wm = (wid >> 1) * 32;   // warp row offset in tile
    const int wn = (wid & 1) * 64;    // warp col offset in tile

    wmma::fragment<wmma::accumulator, 16, 16, 8, float> cf[2][4];
#pragma unroll
    for (int mf = 0; mf < 2; mf++)
#pragma unroll
        for (int nf = 0; nf < 4; nf++)
            wmma::fill_fragment(cf[mf][nf], 0.0f);

    for (int kk = 0; kk < K; kk += 32) {
        // stage A: 128x32 floats = 1024 float4 (4 per thread)
#pragma unroll
        for (int it = 0; it < 4; it++) {
            int idx = tid + it * 256;
            int m = idx >> 3;
            int k4 = (idx & 7) << 2;
            int row = row0 + m;
            float4 v = make_float4(0.f, 0.f, 0.f, 0.f);
            if (row < M) v = *(const float4*)(A + (long)row * lda + kk + k4);
            *(float4*)(As + m * AS_STRIDE + k4) = v;
        }
        // stage B: 32x128 floats
#pragma unroll
        for (int it = 0; it < 4; it++) {
            int idx = tid + it * 256;
            int kb = idx >> 5;
            int n4 = (idx & 31) << 2;
            *(float4*)(Bs + kb * BS_STRIDE + n4) =
                *(const float4*)(B + (long)(kk + kb) * 128 + n4);
        }
        __syncthreads();

#pragma unroll
        for (int ks = 0; ks < 4; ks++) {
            const int k0 = ks * 8;
            wmma::fragment<wmma::matrix_a, 16, 16, 8, wmma::precision::tf32,
                           wmma::row_major> af[2];
            wmma::fragment<wmma::matrix_b, 16, 16, 8, wmma::precision::tf32,
                           wmma::row_major> bf[4];
#pragma unroll
            for (int mf = 0; mf < 2; mf++) {
                wmma::load_matrix_sync(af[mf],
                    As + (wm + mf * 16) * AS_STRIDE + k0, AS_STRIDE);
#pragma unroll
                for (int e = 0; e < af[mf].num_elements; e++)
                    af[mf].x[e] = wmma::__float_to_tf32(af[mf].x[e]);
            }
#pragma unroll
            for (int nf = 0; nf < 4; nf++) {
                wmma::load_matrix_sync(bf[nf],
                    Bs + k0 * BS_STRIDE + wn + nf * 16, BS_STRIDE);
#pragma unroll
                for (int e = 0; e < bf[nf].num_elements; e++)
                    bf[nf].x[e] = wmma::__float_to_tf32(bf[nf].x[e]);
            }
#pragma unroll
            for (int mf = 0; mf < 2; mf++)
#pragma unroll
                for (int nf = 0; nf < 4; nf++)
                    wmma::mma_sync(cf[mf][nf], af[mf], bf[nf], cf[mf][nf]);
        }
        __syncthreads();
    }

    // ---- epilogue: per-fragment dump to per-warp scratch, then fused ops ----
    const int er = lane >> 1;          // row within fragment 0..15
    const int ec = (lane & 1) * 8;     // col half 0 or 8
#pragma unroll
    for (int mf = 0; mf < 2; mf++) {
#pragma unroll
        for (int nf = 0; nf < 4; nf++) {
            wmma::store_matrix_sync(&Cs[wid][0], cf[mf][nf], 16,
                                    wmma::mem_row_major);
            __syncwarp();
            int row = row0 + wm + mf * 16 + er;
            int col = wn + nf * 16 + ec;
            if (row < M) {
                const float* ws = &Cs[wid][er * 16 + ec];
                float v[8];
#pragma unroll
                for (int q = 0; q < 8; q++) v[q] = ws[q];
                if (MODE == 0) {
                    if (bias)
#pragma unroll
                        for (int q = 0; q < 8; q++) v[q] += bias[col + q];
                } else if (MODE == 1 || MODE == 2) {
                    const float* Pr = P + (long)i1[row] * 128 + col;
                    const float* Qr = Q + (long)i2[row] * 128 + col;
#pragma unroll
                    for (int q = 0; q < 8; q++) {
                        v[q] += bias[col + q] + Pr[q] + Qr[q];
                        if (MODE == 2) v[q] = fmaxf(v[q], 0.f);
                    }
                } else { // MODE 3
                    const float* Rr = R + (long)row * 128 + col;
#pragma unroll
                    for (int q = 0; q < 8; q++)
                        v[q] = Rr[q] + (v[q] + bias[col + q]) * 0.5f;
                }
                float* crow = C + (long)row * 128 + col;
                *(float4*)(crow) = make_float4(v[0], v[1], v[2], v[3]);
                *(float4*)(crow + 4) = make_float4(v[4], v[5], v[6], v[7]);
            }
            __syncwarp();
        }
    }
}

// ---------------- small kernels ----------------
__global__ void zero_k() {
    int i = blockIdx.x * blockDim.x + threadIdx.x;
    if (i < N_NODES) g_deg[i] = 0;
    if (i < H) { g_bnsum[i] = 0.f; g_bnsq[i] = 0.f; }
}

__global__ void foldbias_k(const float* __restrict__ be, const float* __restrict__ bpre,
                           const float* __restrict__ Wpre, const float* __restrict__ bpost,
                           const float* __restrict__ blin, const float* __restrict__ Wlin) {
    int j = threadIdx.x; // 128
    float s = bpre[j];
    for (int k = 0; k < H; k++) s += be[k] * Wpre[(2 * H + k) * H + j];
    g_bh[j] = s;
    float t = blin[j];
    for (int k = 0; k < H; k++) t += bpost[k] * Wlin[k * H + j];
    g_b13[j] = t;
}

__global__ void hist_k(const int* __restrict__ dst) {
    int e = blockIdx.x * blockDim.x + threadIdx.x;
    if (e < N_EDGES) atomicAdd(&g_deg[dst[e]], 1);
}

__global__ void scan_k() {
    const int CH = 49; // 1024*49 >= 50000
    int t = threadIdx.x;
    int begin = t * CH;
    int end = min(begin + CH, N_NODES);
    int s = 0;
    for (int i = begin; i < end; i++) s += g_deg[i];
    __shared__ int sums[1024];
    sums[t] = s;
    __syncthreads();
    for (int off = 1; off < 1024; off <<= 1) {
        int v = (t >= off) ? sums[t - off] : 0;
        __syncthreads();
        sums[t] += v;
        __syncthreads();
    }
    int running = (t == 0) ? 0 : sums[t - 1];
    for (int i = begin; i < end; i++) {
        g_off[i] = running;
        g_cur[i] = running;
        running += g_deg[i];
    }
    if (t == 1023) g_off[N_NODES] = sums[1023];
}

__global__ void scatter_k(const int* __restrict__ dst) {
    int e = blockIdx.x * blockDim.x + threadIdx.x;
    if (e < N_EDGES) {
        int p = atomicAdd(&g_cur[dst[e]], 1);
        g_perm[p] = e;
    }
}

// per-node PNA aggregation; writes full A13 row (x copy + 12H scaled aggregates)
__global__ void reduce_k(const float* __restrict__ h, const float* __restrict__ x,
                         float* __restrict__ A13) {
    int node = blockIdx.x;
    int c = threadIdx.x; // 128
    int s = g_off[node], e = g_off[node + 1];
    float sum = 0.f, sum2 = 0.f, mx = -INFINITY, mn = INFINITY;
    for (int i = s; i < e; i++) {
        int ed = g_perm[i];
        float v = h[(long)ed * 128 + c];
        sum += v;
        sum2 += v * v;
        mx = fmaxf(mx, v);
        mn = fminf(mn, v);
    }
    int deg = e - s;
    float degc = fmaxf((float)deg, 1.f);
    float mean = sum / degc;
    float mean2 = sum2 / degc;
    float sd = sqrtf(fmaxf(mean2 - mean * mean, 0.f) + 1e-5f);
    if (deg == 0) { mx = 0.f; mn = 0.f; }
    float logd = logf(degc + 1.f);
    float s1 = logd / LOG17;
    float s2 = LOG17 / logd;
    float* row = A13 + (long)node * H13;
    row[c] = x[(long)node * 128 + c];
    row[128 + c] = mean;
    row[256 + c] = mx;
    row[384 + c] = mn;
    row[512 + c] = sd;
    row[640 + c] = mean * s1;
    row[768 + c] = mx * s1;
    row[896 + c] = mn * s1;
    row[1024 + c] = sd * s1;
    row[1152 + c] = mean * s2;
    row[1280 + c] = mx * s2;
    row[1408 + c] = mn * s2;
    row[1536 + c] = sd * s2;
}

__global__ void bn_partial_k(const float* __restrict__ out) {
    int c = threadIdx.x; // 128
    float s = 0.f, s2 = 0.f;
    for (int r = blockIdx.x; r < N_NODES; r += gridDim.x) {
        float v = out[(long)r * 128 + c];
        s += v;
        s2 += v * v;
    }
    atomicAdd(&g_bnsum[c], s);
    atomicAdd(&g_bnsq[c], s2);
}

__global__ void bn_final_k() {
    int c = threadIdx.x;
    float mu = g_bnsum[c] / (float)N_NODES;
    float var = g_bnsq[c] / (float)N_NODES - mu * mu;
    g_mu[c] = mu;
    g_istd[c] = rsqrtf(var + 1e-5f);
}

__global__ void xnew_k(const float* __restrict__ out, const float* __restrict__ x,
                       const float* __restrict__ gam, const float* __restrict__ bet,
                       float* __restrict__ xnew) {
    long i = (long)blockIdx.x * blockDim.x + threadIdx.x;
    if (i >= (long)N_NODES * H) return;
    int c = (int)(i & 127);
    float v = (out[i] - g_mu[c]) * g_istd[c] * gam[c] + bet[c];
    xnew[i] = 0.5f * (x[i] + fmaxf(v, 0.f));
}

// ---------------- launch ----------------
extern "C" void kernel_launch(void* const* d_in, const int* in_sizes, int n_in,
                              void* d_out, int out_size) {
    const float* x      = (const float*)d_in[0];
    const float* eattr  = (const float*)d_in[1];
    const float* We     = (const float*)d_in[2];
    const float* be     = (const float*)d_in[3];
    const float* Wpre   = (const float*)d_in[4];
    const float* bpre   = (const float*)d_in[5];
    const float* Wpost  = (const float*)d_in[6];
    const float* bpost  = (const float*)d_in[7];
    const float* Wlin   = (const float*)d_in[8];
    const float* blin   = (const float*)d_in[9];
    const float* bn_g   = (const float*)d_in[10];
    const float* bn_b   = (const float*)d_in[11];
    const float* W1     = (const float*)d_in[12];
    const float* b1     = (const float*)d_in[13];
    const float* W2     = (const float*)d_in[14];
    const float* b2     = (const float*)d_in[15];
    const int*   eidx   = (const int*)d_in[16];
    const int* src = eidx;
    const int* dst = eidx + N_EDGES;

    float* o = (float*)d_out;
    float* o_x = o;                         // x_new [N,H]
    float* o_e = o + (long)N_NODES * H;     // e_new [E,H]

    float *xd, *xs, *h, *A13, *outb, *Wef, *W13, *bh, *b13;
    cudaGetSymbolAddress((void**)&xd, g_xd);
    cudaGetSymbolAddress((void**)&xs, g_xs);
    cudaGetSymbolAddress((void**)&h, g_h);
    cudaGetSymbolAddress((void**)&A13, g_A13);
    cudaGetSymbolAddress((void**)&outb, g_outb);
    cudaGetSymbolAddress((void**)&Wef, g_Wef);
    cudaGetSymbolAddress((void**)&W13, g_W13);
    cudaGetSymbolAddress((void**)&bh, g_bh);
    cudaGetSymbolAddress((void**)&b13, g_b13);

    const int GN = (N_NODES + 127) / 128;   // 391
    const int GE = (N_EDGES + 127) / 128;   // 4688
    const int TE = (N_EDGES + 255) / 256;

    // 0) zero counters
    zero_k<<<(N_NODES + 255) / 256, 256>>>();
    // 1) fold biases + weights
    foldbias_k<<<1, 128>>>(be, bpre, Wpre, bpost, blin, Wlin);
    wgemm<0><<<1, 256>>>(We, H, Wpre + 2 * H * H, nullptr, Wef, H, H,
                         nullptr, nullptr, nullptr, nullptr, nullptr);
    wgemm<0><<<13, 256>>>(Wpost, H, Wlin, nullptr, W13, H13, H,
                          nullptr, nullptr, nullptr, nullptr, nullptr);
    // 2) node pre-projections
    wgemm<0><<<GN, 256>>>(x, H, Wpre, nullptr, xd, N_NODES, H,
                          nullptr, nullptr, nullptr, nullptr, nullptr);
    wgemm<0><<<GN, 256>>>(x, H, Wpre + H * H, nullptr, xs, N_NODES, H,
                          nullptr, nullptr, nullptr, nullptr, nullptr);
    // 3) dst-CSR
    hist_k<<<TE, 256>>>(dst);
    scan_k<<<1, 1024>>>();
    scatter_k<<<TE, 256>>>(dst);
    // 4) h = edge_attr @ Wef + bh + xd[dst] + xs[src]
    wgemm<1><<<GE, 256>>>(eattr, H, Wef, bh, h, N_EDGES, H,
                          dst, src, xd, xs, nullptr);
    // 5) PNA aggregation -> A13
    reduce_k<<<N_NODES, 128>>>(h, x, A13);
    // 6) out = A13 @ W13 + b13
    wgemm<0><<<GN, 256>>>(A13, H13, W13, b13, outb, N_NODES, H13,
                          nullptr, nullptr, nullptr, nullptr, nullptr);
    // 7) BN + relu + residual -> x_new (into d_out)
    bn_partial_k<<<256, 128>>>(outb);
    bn_final_k<<<1, 128>>>();
    xnew_k<<<(N_NODES * H + 255) / 256, 256>>>(outb, x, bn_g, bn_b, o_x);
    // 8) edge-update node projections (reuse xd/xs as ys/yd)
    wgemm<0><<<GN, 256>>>(o_x, H, W1, nullptr, xd, N_NODES, H,
                          nullptr, nullptr, nullptr, nullptr, nullptr);
    wgemm<0><<<GN, 256>>>(o_x, H, W1 + H * H, nullptr, xs, N_NODES, H,
                          nullptr, nullptr, nullptr, nullptr, nullptr);
    // 9) z = relu(edge_attr @ W1[2H:] + b1 + ys[src] + yd[dst]) (reuse h)
    wgemm<2><<<GE, 256>>>(eattr, H, W1 + 2 * H * H, b1, h, N_EDGES, H,
                          src, dst, xd, xs, nullptr);
    // 10) e_new = edge_attr + (z @ W2 + b2) * 0.5
    wgemm<3><<<GE, 256>>>(h, H, W2, b2, o_e, N_EDGES, H,
                          nullptr, nullptr, nullptr, nullptr, eattr);
    (void)in_sizes; (void)n_in; (void)out_size;
}